// round 14
// baseline (speedup 1.0000x reference)
#include <cuda_runtime.h>
#include <cuda_fp16.h>
#include <math.h>
#include <stdint.h>

// ---------------- problem constants ----------------
#define B_SZ     2
#define S_LEN    2048
#define D_MODEL  1024
#define NUM_H    16
#define HEAD_D   64
#define FF_DIM   4096
#define N_TOK    (B_SZ * S_LEN)        // 4096
#define MAXM1    4999                  // MAX_SEQ_LEN - 1
#define MEG      (1024 * 1024)
#define QKV_N    3072
#define BT_ELEMS ((2 * MAXM1 + 1) * NUM_H)   // 159984

// ---------------- scratch (static device globals; no allocation) ----------------
__device__ float  g_x1 [N_TOK * D_MODEL];
__device__ float  g_bqkv[QKV_N];
__device__ float  g_bt2[BT_ELEMS];               // bias * log2(e) - 6
__device__ __half g_a  [N_TOK * D_MODEL];        // LN output (fp16)
__device__ __half g_qkv[(size_t)N_TOK * QKV_N];  // interleaved q|k|v per token
__device__ __half g_c  [N_TOK * D_MODEL];        // attention ctx
__device__ __half g_h  [N_TOK * FF_DIM];         // FFN hidden
__device__ __half g_w  [12 * MEG];               // all weights [N,K] fp16
__device__ unsigned long long g_mpk[(size_t)B_SZ * S_LEN * (S_LEN / 64)];

// ---------------- PTX helpers (portable sm_80+ only) ----------------
__device__ __forceinline__ uint32_t smem_u32(const void* p) {
    uint32_t a;
    asm("{ .reg .u64 t; cvta.to.shared.u64 t, %1; cvt.u32.u64 %0, t; }" : "=r"(a) : "l"(p));
    return a;
}

#define CP_ASYNC16(saddr, gptr) \
    asm volatile("cp.async.cg.shared.global [%0], [%1], 16;" :: "r"(saddr), "l"(gptr))
#define CP_ASYNC4(saddr, gptr) \
    asm volatile("cp.async.ca.shared.global [%0], [%1], 4;" :: "r"(saddr), "l"(gptr))
#define CP_COMMIT() asm volatile("cp.async.commit_group;" ::: "memory")
#define CP_WAIT(n)  asm volatile("cp.async.wait_group %0;" :: "n"(n) : "memory")

#define LDSM_X4(r0, r1, r2, r3, addr) \
    asm volatile("ldmatrix.sync.aligned.m8n8.x4.shared.b16 {%0,%1,%2,%3}, [%4];" \
                 : "=r"(r0), "=r"(r1), "=r"(r2), "=r"(r3) : "r"(addr))
#define LDSM_X4_T(r0, r1, r2, r3, addr) \
    asm volatile("ldmatrix.sync.aligned.m8n8.x4.trans.shared.b16 {%0,%1,%2,%3}, [%4];" \
                 : "=r"(r0), "=r"(r1), "=r"(r2), "=r"(r3) : "r"(addr))

__device__ __forceinline__ void mma16816(float* c, const uint32_t* a, const uint32_t* b) {
    asm volatile("mma.sync.aligned.m16n8k16.row.col.f32.f16.f16.f32 "
        "{%0,%1,%2,%3}, {%4,%5,%6,%7}, {%8,%9}, {%0,%1,%2,%3};"
        : "+f"(c[0]), "+f"(c[1]), "+f"(c[2]), "+f"(c[3])
        : "r"(a[0]), "r"(a[1]), "r"(a[2]), "r"(a[3]), "r"(b[0]), "r"(b[1]));
}

__device__ __forceinline__ uint32_t pack_h(float a, float b) {
    __half2 t = __floats2half2_rn(a, b);
    return *(uint32_t*)&t;
}

__device__ __forceinline__ float ex2f(float x) {
    float y;
    asm("ex2.approx.ftz.f32 %0, %1;" : "=f"(y) : "f"(x));
    return y;
}

// ---------------- LayerNorm row (shared by ln_kernel and prep_kernel) ----------------
__device__ __forceinline__ void ln_row(
    const float* __restrict__ x, const float* __restrict__ gamma,
    const float* __restrict__ beta, __half* __restrict__ o, int row, int tid)
{
    const float4* xr = (const float4*)(x + (size_t)row * D_MODEL);
    float4 v = xr[tid];
    float s  = v.x + v.y + v.z + v.w;
    float ss = v.x*v.x + v.y*v.y + v.z*v.z + v.w*v.w;
    #pragma unroll
    for (int of = 16; of; of >>= 1) {
        s  += __shfl_xor_sync(0xffffffffu, s,  of);
        ss += __shfl_xor_sync(0xffffffffu, ss, of);
    }
    __shared__ float rs[8], rss[8];
    int w = tid >> 5;
    if ((tid & 31) == 0) { rs[w] = s; rss[w] = ss; }
    __syncthreads();
    float S0 = 0.f, SS0 = 0.f;
    #pragma unroll
    for (int i = 0; i < 8; i++) { S0 += rs[i]; SS0 += rss[i]; }
    float mean = S0 * (1.0f / D_MODEL);
    float var  = SS0 * (1.0f / D_MODEL) - mean * mean;
    float rstd = rsqrtf(var + 1e-5f);
    float4 gg = ((const float4*)gamma)[tid];
    float4 bb = ((const float4*)beta)[tid];
    float o0 = (v.x - mean) * rstd * gg.x + bb.x;
    float o1 = (v.y - mean) * rstd * gg.y + bb.y;
    float o2 = (v.z - mean) * rstd * gg.z + bb.z;
    float o3 = (v.w - mean) * rstd * gg.w + bb.w;
    size_t base = (size_t)row * D_MODEL + tid * 4;
    *(uint2*)&o[base] = make_uint2(pack_h(o0, o1), pack_h(o2, o3));
}

__global__ __launch_bounds__(256) void ln_kernel(
    const float* __restrict__ x, const float* __restrict__ gamma,
    const float* __restrict__ beta, __half* __restrict__ o)
{
    ln_row(x, gamma, beta, o, blockIdx.x, threadIdx.x);
}

// ---------------- fused preprocessing (weights + bias + mask + bt2 + LN1) ----------------
//  [0, 4096):       wq/wk/wv/wo transposes
//  [4096, 8192):    w1
//  [8192, 12288):   w2
//  [12288, 12300):  bias concat
//  [12300, 12812):  mask pack
//  [12812, 13437):  bias table pre-scale (log2e, -6 shift)
//  [13437, 17533):  LN1 rows (4096)
#define PREP_BLOCKS 17533

__device__ __forceinline__ void transpose_blk(
    const float* __restrict__ src, __half* __restrict__ dst,
    int K, int N, int nb, int kb, int tx, int ty, float (*tile)[33])
{
    int n0 = nb * 32, k0 = kb * 32;
    #pragma unroll
    for (int r = 0; r < 4; r++)
        tile[ty + 8 * r][tx] = src[(size_t)(k0 + ty + 8 * r) * N + n0 + tx];
    __syncthreads();
    #pragma unroll
    for (int r = 0; r < 4; r++) {
        float v = tile[tx][ty + 8 * r];
        size_t o = (size_t)(n0 + ty + 8 * r) * K + k0 + tx;
        dst[o] = __float2half_rn(v);
    }
}

__global__ __launch_bounds__(256) void prep_kernel(
    const float* __restrict__ wq, const float* __restrict__ wk,
    const float* __restrict__ wv, const float* __restrict__ wo,
    const float* __restrict__ w1, const float* __restrict__ w2,
    __half* __restrict__ w,
    const float* __restrict__ bq, const float* __restrict__ bk,
    const float* __restrict__ bv, float* __restrict__ bqkv,
    const int* __restrict__ mask, unsigned long long* __restrict__ mpk,
    const float* __restrict__ bt, float* __restrict__ bt2,
    const float* __restrict__ x, const float* __restrict__ g1,
    const float* __restrict__ be1, __half* __restrict__ a)
{
    __shared__ float tile[32][33];
    int bid = blockIdx.x;
    int tx = threadIdx.x, ty = threadIdx.y;
    int ft = ty * 32 + tx;

    if (bid < 4096) {
        int which = bid >> 10, r = bid & 1023;
        const float* src = which == 0 ? wq : which == 1 ? wk : which == 2 ? wv : wo;
        transpose_blk(src, w + (size_t)which * MEG, 1024, 1024, r & 31, r >> 5, tx, ty, tile);
    } else if (bid < 8192) {
        int r = bid - 4096;
        transpose_blk(w1, w + 4 * MEG, 1024, 4096, r & 127, r >> 7, tx, ty, tile);
    } else if (bid < 12288) {
        int r = bid - 8192;
        transpose_blk(w2, w + 8 * MEG, 4096, 1024, r & 31, r >> 5, tx, ty, tile);
    } else if (bid < 12300) {
        int i = (bid - 12288) * 256 + ft;
        if (i < QKV_N)
            bqkv[i] = i < 1024 ? bq[i] : (i < 2048 ? bk[i - 1024] : bv[i - 2048]);
    } else if (bid < 12812) {
        int idx = (bid - 12300) * 256 + ft;
        const int4* p = (const int4*)mask + (size_t)idx * 16;
        unsigned long long wv64 = 0;
        #pragma unroll
        for (int i = 0; i < 16; i++) {
            int4 v = p[i];
            wv64 |= (unsigned long long)(v.x != 0) << (i * 4 + 0);
            wv64 |= (unsigned long long)(v.y != 0) << (i * 4 + 1);
            wv64 |= (unsigned long long)(v.z != 0) << (i * 4 + 2);
            wv64 |= (unsigned long long)(v.w != 0) << (i * 4 + 3);
        }
        mpk[idx] = wv64;
    } else if (bid < 13437) {
        int i = (bid - 12812) * 256 + ft;
        if (i < BT_ELEMS)
            bt2[i] = bt[i] * 1.4426950408889634f - 6.0f;
    } else {
        ln_row(x, g1, be1, a, bid - 13437, ft);
    }
}

// ---------------- fp16 GEMM (2-stage cp.async pipeline — proven config) ----------------
// EPI: 1 bias+GELU -> fp16, 2 bias+residual -> fp32, 5 bias -> fp16
__device__ __forceinline__ float gelu_exact(float x) {
    return 0.5f * x * (1.0f + erff(x * 0.70710678118654752f));
}

#define GM_A     0
#define GM_B     16384
#define GM_SSZ   32768
#define GM_SMEM  (2 * GM_SSZ)

template<int EPI>
__global__ __launch_bounds__(256) void gemm_mma(
    const __half* __restrict__ A, const __half* __restrict__ B,
    const float* __restrict__ bias, const float* __restrict__ res,
    float* __restrict__ C, __half* __restrict__ Ch, int M, int N, int K)
{
    extern __shared__ char smem[];
    uint32_t base = smem_u32(smem);
    int tid  = threadIdx.x;
    int lane = tid & 31;
    int wid  = tid >> 5;
    int warp_m = wid & 3;
    int warp_n = wid >> 2;
    int bm = blockIdx.y * 128, bn = blockIdx.x * 128;

    float acc[2][8][4];
    #pragma unroll
    for (int i = 0; i < 2; i++)
        #pragma unroll
        for (int j = 0; j < 8; j++)
            #pragma unroll
            for (int t = 0; t < 4; t++) acc[i][j][t] = 0.f;

    auto load_tile = [&](uint32_t sdst, const __half* g, int rowBase, int k0) {
        #pragma unroll
        for (int i = 0; i < 4; i++) {
            int f = i * 256 + tid;
            int row = f >> 3, c = f & 7;
            const __half* gp = g + (size_t)(rowBase + row) * K + k0 + c * 8;
            uint32_t off = row * 128 + c * 16;
            uint32_t sw = off ^ ((off >> 3) & 0x70);
            CP_ASYNC16(sdst + sw, gp);
        }
    };
    auto load_chunk = [&](int stage, int k0) {
        uint32_t sb = base + stage * GM_SSZ;
        load_tile(sb + GM_A, A, bm, k0);
        load_tile(sb + GM_B, B, bn, k0);
        CP_COMMIT();
    };

    int a_row = warp_m * 32 + (lane & 15);
    int a_kh  = lane >> 4;
    int b_row = warp_n * 64 + ((lane >> 4) & 1) * 8 + (lane & 7);
    int b_kh  = (lane >> 3) & 1;

    int nCh = K >> 6;
    load_chunk(0, 0);

    for (int it = 0; it < nCh; it++) {
        int buf = it & 1;
        if (it + 1 < nCh) { load_chunk(buf ^ 1, (it + 1) << 6); CP_WAIT(1); }
        else              { CP_WAIT(0); }
        __syncthreads();

        uint32_t sb = base + buf * GM_SSZ;
        #pragma unroll
        for (int ks = 0; ks < 4; ks++) {
            uint32_t ah[2][4];
            #pragma unroll
            for (int mf = 0; mf < 2; mf++) {
                int row = a_row + mf * 16;
                uint32_t col = (uint32_t)((ks * 2 + a_kh) ^ (row & 7)) * 16;
                uint32_t ad = sb + GM_A + row * 128 + col;
                LDSM_X4(ah[mf][0], ah[mf][1], ah[mf][2], ah[mf][3], ad);
            }
            #pragma unroll
            for (int nfp = 0; nfp < 4; nfp++) {
                int row = b_row + nfp * 16;
                uint32_t col = (uint32_t)((ks * 2 + b_kh) ^ (row & 7)) * 16;
                uint32_t bh[4];
                uint32_t bd = sb + GM_B + row * 128 + col;
                LDSM_X4(bh[0], bh[1], bh[2], bh[3], bd);
                #pragma unroll
                for (int mf = 0; mf < 2; mf++) {
                    #pragma unroll
                    for (int nn = 0; nn < 2; nn++)
                        mma16816(acc[mf][nfp * 2 + nn], ah[mf], &bh[nn * 2]);
                }
            }
        }
        __syncthreads();
    }

    int mrow0 = bm + warp_m * 32 + (lane >> 2);
    int ncol0 = bn + warp_n * 64 + (lane & 3) * 2;
    #pragma unroll
    for (int mf = 0; mf < 2; mf++) {
        #pragma unroll
        for (int nf = 0; nf < 8; nf++) {
            int n = ncol0 + nf * 8;
            float b0 = bias[n], b1 = bias[n + 1];
            #pragma unroll
            for (int half = 0; half < 2; half++) {
                int m = mrow0 + mf * 16 + half * 8;
                float v0 = acc[mf][nf][half * 2 + 0] + b0;
                float v1 = acc[mf][nf][half * 2 + 1] + b1;
                size_t o = (size_t)m * N + n;
                if (EPI == 1) {
                    v0 = gelu_exact(v0); v1 = gelu_exact(v1);
                    *(uint32_t*)&Ch[o] = pack_h(v0, v1);
                } else if (EPI == 2) {
                    float2 rv = *(const float2*)&res[o];
                    *(float2*)&C[o] = make_float2(v0 + rv.x, v1 + rv.y);
                } else {
                    *(uint32_t*)&Ch[o] = pack_h(v0, v1);
                }
            }
        }
    }
}

// ---------------- flash attention (fp16 mma, no-max softmax, half-tile scores) ----------------
// grid (S/64, H, B), block 128 (4 warps x m16), 4 CTAs/SM (proven sweet spot)
#define AT_Q     0
#define AT_ST    8192
#define AT_K     0
#define AT_V     8192
#define AT_BIAS  16384
#define AT_SSZ   16896
#define AT_SMEM  (AT_ST + 2 * AT_SSZ)

__global__ __launch_bounds__(128, 4) void attn_mma(
    const __half* __restrict__ qkv, const float* __restrict__ bt2,
    const unsigned long long* __restrict__ mpk, __half* __restrict__ Oh)
{
    extern __shared__ char smem[];
    uint32_t base = smem_u32(smem);

    int b  = blockIdx.z, h = blockIdx.y;
    int q0 = blockIdx.x * 64;
    int tid  = threadIdx.x;
    int lane = tid & 31;
    int wid  = tid >> 5;
    int headoff = h * HEAD_D;

    // ---- Q tile load (64 x 64) ----
    #pragma unroll
    for (int i = 0; i < 4; i++) {
        int f = i * 128 + tid;
        int row = f >> 3, c = f & 7;
        uint32_t sw = row * 128 + (uint32_t)((c ^ (row & 7)) * 16);
        const __half* gp = qkv + ((size_t)(b * S_LEN + q0 + row)) * QKV_N + headoff + c * 8;
        CP_ASYNC16(base + AT_Q + sw, gp);
    }
    CP_COMMIT();

    auto load_kv = [&](int s, int kt) {
        uint32_t sb = base + AT_ST + s * AT_SSZ;
        int kr = kt * 64;
        #pragma unroll
        for (int i = 0; i < 4; i++) {
            int f = i * 128 + tid;
            int row = f >> 3, c = f & 7;
            uint32_t sw = row * 128 + (uint32_t)((c ^ (row & 7)) * 16);
            size_t gb = ((size_t)(b * S_LEN + kr + row)) * QKV_N + c * 8;
            CP_ASYNC16(sb + AT_K + sw, qkv + gb + 1024 + headoff);
            CP_ASYNC16(sb + AT_V + sw, qkv + gb + 2048 + headoff);
        }
        int d = kr - q0 + tid - 63 + MAXM1;
        CP_ASYNC4(sb + AT_BIAS + tid * 4, bt2 + (size_t)d * NUM_H + h);
        CP_COMMIT();
    };

    load_kv(0, 0);
    CP_WAIT(0);
    __syncthreads();

    // ---- hoist Q fragments ----
    int a_row = wid * 16 + (lane & 15);
    int a_kh  = lane >> 4;
    uint32_t qh[4][4];
    #pragma unroll
    for (int ks = 0; ks < 4; ks++) {
        uint32_t col = (uint32_t)(((ks * 2 + a_kh) ^ (a_row & 7)) * 16);
        uint32_t ad = base + AT_Q + a_row * 128 + col;
        LDSM_X4(qh[ks][0], qh[ks][1], qh[ks][2], qh[ks][3], ad);
    }

    float ctx[8][4];
    #pragma unroll
    for (int i = 0; i < 8; i++)
        #pragma unroll
        for (int j = 0; j < 4; j++) ctx[i][j] = 0.f;
    float l0 = 0.f, l1 = 0.f;

    int r_loc0 = wid * 16 + (lane >> 2);
    int cbase  = (lane & 3) * 2;
    int b_row_base = ((lane >> 4) & 1) * 8 + (lane & 7);
    int b_kh = (lane >> 3) & 1;
    int v_i  = lane >> 3, v_j = lane & 7;
    const float csc = 0.125f * 1.4426950408889634f;   // score scale in log2 domain

    const unsigned long long* mp0 = mpk + ((size_t)(b * S_LEN) + q0 + r_loc0) * (S_LEN / 64);
    const unsigned long long* mp1 = mpk + ((size_t)(b * S_LEN) + q0 + r_loc0 + 8) * (S_LEN / 64);

    const int nKT = S_LEN / 64;
    unsigned long long mw0 = mp0[0], mw1 = mp1[0];

    for (int kt = 0; kt < nKT; kt++) {
        int s = kt & 1;
        if (kt + 1 < nKT) { load_kv(s ^ 1, kt + 1); CP_WAIT(1); }
        else              { CP_WAIT(0); }
        __syncthreads();
        uint32_t sb = base + AT_ST + s * AT_SSZ;
        const float* bs = (const float*)(smem + AT_ST + s * AT_SSZ + AT_BIAS);

        bool allm = ((mw0 & mw1) == ~0ull);
        unsigned long long cw0 = mw0, cw1 = mw1;
        if (kt + 1 < nKT) { mw0 = mp0[kt + 1]; mw1 = mp1[kt + 1]; }

        #pragma unroll
        for (int ph = 0; ph < 2; ph++) {
            float sacc[4][4];
            #pragma unroll
            for (int i = 0; i < 4; i++)
                #pragma unroll
                for (int j = 0; j < 4; j++) sacc[i][j] = 0.f;

            #pragma unroll
            for (int ks = 0; ks < 4; ks++) {
                #pragma unroll
                for (int g2 = 0; g2 < 2; g2++) {
                    int g = ph * 2 + g2;
                    int row = g * 16 + b_row_base;
                    uint32_t col = (uint32_t)(((ks * 2 + b_kh) ^ (row & 7)) * 16);
                    uint32_t bh[4];
                    uint32_t bd = sb + AT_K + row * 128 + col;
                    LDSM_X4(bh[0], bh[1], bh[2], bh[3], bd);
                    mma16816(sacc[2*g2],   qh[ks], &bh[0]);
                    mma16816(sacc[2*g2+1], qh[ks], &bh[2]);
                }
            }

            float rs0 = 0.f, rs1 = 0.f;
            #pragma unroll
            for (int fl = 0; fl < 4; fl++) {
                int c0 = (ph * 4 + fl) * 8 + cbase;
                int i0 = c0 - r_loc0 + 63;
                float p00 = ex2f(sacc[fl][0] * csc + bs[i0]);
                float p01 = ex2f(sacc[fl][1] * csc + bs[i0 + 1]);
                float p10 = ex2f(sacc[fl][2] * csc + bs[i0 - 8]);
                float p11 = ex2f(sacc[fl][3] * csc + bs[i0 - 7]);
                if (!allm) {
                    p00 = ((cw0 >> c0) & 1)       ? p00 : 0.f;
                    p01 = ((cw0 >> (c0 + 1)) & 1) ? p01 : 0.f;
                    p10 = ((cw1 >> c0) & 1)       ? p10 : 0.f;
                    p11 = ((cw1 >> (c0 + 1)) & 1) ? p11 : 0.f;
                }
                sacc[fl][0] = p00; sacc[fl][1] = p01; sacc[fl][2] = p10; sacc[fl][3] = p11;
                rs0 += p00 + p01; rs1 += p10 + p11;
            }
            l0 += rs0; l1 += rs1;

            #pragma unroll
            for (int ksl = 0; ksl < 2; ksl++) {
                int ks = ph * 2 + ksl;
                uint32_t pf[4];
                pf[0] = pack_h(sacc[2*ksl][0],   sacc[2*ksl][1]);
                pf[1] = pack_h(sacc[2*ksl][2],   sacc[2*ksl][3]);
                pf[2] = pack_h(sacc[2*ksl+1][0], sacc[2*ksl+1][1]);
                pf[3] = pack_h(sacc[2*ksl+1][2], sacc[2*ksl+1][3]);
                #pragma unroll
                for (int vg = 0; vg < 4; vg++) {
                    int row = ks * 16 + (v_i & 1) * 8 + v_j;
                    uint32_t chunk = (uint32_t)(vg * 2 + (v_i >> 1));
                    uint32_t vd = sb + AT_V + row * 128 + ((chunk ^ (row & 7)) * 16);
                    uint32_t vb[4];
                    LDSM_X4_T(vb[0], vb[1], vb[2], vb[3], vd);
                    mma16816(ctx[2*vg],   pf, &vb[0]);
                    mma16816(ctx[2*vg+1], pf, &vb[2]);
                }
            }
        }
        __syncthreads();
    }

    l0 += __shfl_xor_sync(0xffffffffu, l0, 1);
    l0 += __shfl_xor_sync(0xffffffffu, l0, 2);
    l1 += __shfl_xor_sync(0xffffffffu, l1, 1);
    l1 += __shfl_xor_sync(0xffffffffu, l1, 2);

    float inv0 = 1.0f / l0, inv1 = 1.0f / l1;
    size_t tok0 = (size_t)(b * S_LEN + q0 + r_loc0);
    #pragma unroll
    for (int nf = 0; nf < 8; nf++) {
        int col = headoff + nf * 8 + cbase;
        *(uint32_t*)&Oh[tok0 * D_MODEL + col]       = pack_h(ctx[nf][0] * inv0, ctx[nf][1] * inv0);
        *(uint32_t*)&Oh[(tok0 + 8) * D_MODEL + col] = pack_h(ctx[nf][2] * inv1, ctx[nf][3] * inv1);
    }
}

// ---------------- host orchestration ----------------
extern "C" void kernel_launch(void* const* d_in, const int* in_sizes, int n_in,
                              void* d_out, int out_size)
{
    const float* x    = (const float*)d_in[0];
    const int*   mask = (const int*)  d_in[1];
    const float* wq = (const float*)d_in[2];
    const float* bq = (const float*)d_in[3];
    const float* wk = (const float*)d_in[4];
    const float* bk = (const float*)d_in[5];
    const float* wv = (const float*)d_in[6];
    const float* bv = (const float*)d_in[7];
    const float* wo = (const float*)d_in[8];
    const float* bo = (const float*)d_in[9];
    const float* w1 = (const float*)d_in[10];
    const float* b1 = (const float*)d_in[11];
    const float* w2 = (const float*)d_in[12];
    const float* b2 = (const float*)d_in[13];
    const float* g1  = (const float*)d_in[14];
    const float* be1 = (const float*)d_in[15];
    const float* g2  = (const float*)d_in[16];
    const float* be2 = (const float*)d_in[17];
    const float* bt  = (const float*)d_in[18];

    float *x1, *bqkv, *bt2;
    __half *a, *qkv, *c, *hbuf, *w;
    unsigned long long* mpk;
    cudaGetSymbolAddress((void**)&x1,   g_x1);
    cudaGetSymbolAddress((void**)&bqkv, g_bqkv);
    cudaGetSymbolAddress((void**)&bt2,  g_bt2);
    cudaGetSymbolAddress((void**)&a,    g_a);
    cudaGetSymbolAddress((void**)&qkv,  g_qkv);
    cudaGetSymbolAddress((void**)&c,    g_c);
    cudaGetSymbolAddress((void**)&hbuf, g_h);
    cudaGetSymbolAddress((void**)&w,    g_w);
    cudaGetSymbolAddress((void**)&mpk,  g_mpk);

    float* out = (float*)d_out;

    cudaFuncSetAttribute(gemm_mma<1>, cudaFuncAttributeMaxDynamicSharedMemorySize, GM_SMEM);
    cudaFuncSetAttribute(gemm_mma<2>, cudaFuncAttributeMaxDynamicSharedMemorySize, GM_SMEM);
    cudaFuncSetAttribute(gemm_mma<5>, cudaFuncAttributeMaxDynamicSharedMemorySize, GM_SMEM);
    cudaFuncSetAttribute(attn_mma,    cudaFuncAttributeMaxDynamicSharedMemorySize, AT_SMEM);

    // 0. fused preprocessing (weights/bias/mask/bt2 + LN1)
    prep_kernel<<<PREP_BLOCKS, dim3(32, 8)>>>(wq, wk, wv, wo, w1, w2, w,
                                              bq, bk, bv, bqkv, mask, mpk, bt, bt2,
                                              x, g1, be1, a);

    // 1. fused QKV projection -> interleaved [tok, 3072]
    gemm_mma<5><<<dim3(QKV_N / 128, N_TOK / 128), 256, GM_SMEM>>>(
        a, w, bqkv, nullptr, nullptr, qkv, N_TOK, QKV_N, D_MODEL);

    // 2. attention (64-row q tiles, no-max softmax, 4 CTA/SM)
    attn_mma<<<dim3(S_LEN / 64, NUM_H, B_SZ), 128, AT_SMEM>>>(qkv, bt2, mpk, c);

    // 3. output projection + residual(x) -> x1 fp32
    dim3 gproj(D_MODEL / 128, N_TOK / 128);
    gemm_mma<2><<<gproj, 256, GM_SMEM>>>(c, w + 3 * MEG, bo, x, x1, nullptr, N_TOK, D_MODEL, D_MODEL);

    // 4. pre-norm 2 -> fp16
    ln_kernel<<<N_TOK, 256>>>(x1, g2, be2, a);

    // 5. FFN up + GELU -> fp16
    gemm_mma<1><<<dim3(FF_DIM / 128, N_TOK / 128), 256, GM_SMEM>>>(
        a, w + 4 * MEG, b1, nullptr, nullptr, hbuf, N_TOK, FF_DIM, D_MODEL);

    // 6. FFN down + residual(x1) -> out
    gemm_mma<2><<<gproj, 256, GM_SMEM>>>(hbuf, w + 8 * MEG, b2, x1, out, nullptr, N_TOK, D_MODEL, FF_DIM);

    (void)in_sizes; (void)n_in; (void)out_size;
}

// round 15
// speedup vs baseline: 1.5230x; 1.5230x over previous
#include <cuda_runtime.h>
#include <cuda_fp16.h>
#include <math.h>
#include <stdint.h>

// ---------------- problem constants ----------------
#define B_SZ     2
#define S_LEN    2048
#define D_MODEL  1024
#define NUM_H    16
#define HEAD_D   64
#define FF_DIM   4096
#define N_TOK    (B_SZ * S_LEN)        // 4096
#define MAXM1    4999                  // MAX_SEQ_LEN - 1
#define MEG      (1024 * 1024)
#define QKV_N    3072
#define BT_ELEMS ((2 * MAXM1 + 1) * NUM_H)   // 159984

// ---------------- scratch (static device globals; no allocation) ----------------
__device__ float  g_x1 [N_TOK * D_MODEL];
__device__ float  g_bqkv[QKV_N];
__device__ float  g_bt2[BT_ELEMS];               // bias * log2(e) - 6
__device__ __half g_a  [N_TOK * D_MODEL];        // LN output (fp16)
__device__ __half g_qkv[(size_t)N_TOK * QKV_N];  // interleaved q|k|v per token
__device__ __half g_c  [N_TOK * D_MODEL];        // attention ctx
__device__ __half g_h  [N_TOK * FF_DIM];         // FFN hidden
__device__ __half g_w  [12 * MEG];               // all weights [N,K] fp16
__device__ unsigned long long g_mpk[(size_t)B_SZ * S_LEN * (S_LEN / 64)];

// ---------------- PTX helpers (portable sm_80+ only) ----------------
__device__ __forceinline__ uint32_t smem_u32(const void* p) {
    uint32_t a;
    asm("{ .reg .u64 t; cvta.to.shared.u64 t, %1; cvt.u32.u64 %0, t; }" : "=r"(a) : "l"(p));
    return a;
}

#define CP_ASYNC16(saddr, gptr) \
    asm volatile("cp.async.cg.shared.global [%0], [%1], 16;" :: "r"(saddr), "l"(gptr))
#define CP_ASYNC4(saddr, gptr) \
    asm volatile("cp.async.ca.shared.global [%0], [%1], 4;" :: "r"(saddr), "l"(gptr))
#define CP_COMMIT() asm volatile("cp.async.commit_group;" ::: "memory")
#define CP_WAIT(n)  asm volatile("cp.async.wait_group %0;" :: "n"(n) : "memory")

#define LDSM_X4(r0, r1, r2, r3, addr) \
    asm volatile("ldmatrix.sync.aligned.m8n8.x4.shared.b16 {%0,%1,%2,%3}, [%4];" \
                 : "=r"(r0), "=r"(r1), "=r"(r2), "=r"(r3) : "r"(addr))
#define LDSM_X4_T(r0, r1, r2, r3, addr) \
    asm volatile("ldmatrix.sync.aligned.m8n8.x4.trans.shared.b16 {%0,%1,%2,%3}, [%4];" \
                 : "=r"(r0), "=r"(r1), "=r"(r2), "=r"(r3) : "r"(addr))

__device__ __forceinline__ void mma16816(float* c, const uint32_t* a, const uint32_t* b) {
    asm volatile("mma.sync.aligned.m16n8k16.row.col.f32.f16.f16.f32 "
        "{%0,%1,%2,%3}, {%4,%5,%6,%7}, {%8,%9}, {%0,%1,%2,%3};"
        : "+f"(c[0]), "+f"(c[1]), "+f"(c[2]), "+f"(c[3])
        : "r"(a[0]), "r"(a[1]), "r"(a[2]), "r"(a[3]), "r"(b[0]), "r"(b[1]));
}

__device__ __forceinline__ uint32_t pack_h(float a, float b) {
    __half2 t = __floats2half2_rn(a, b);
    return *(uint32_t*)&t;
}

__device__ __forceinline__ float ex2f(float x) {
    float y;
    asm("ex2.approx.ftz.f32 %0, %1;" : "=f"(y) : "f"(x));
    return y;
}

// ---------------- LayerNorm -> fp16 ----------------
__global__ __launch_bounds__(256) void ln_kernel(
    const float* __restrict__ x, const float* __restrict__ gamma,
    const float* __restrict__ beta, __half* __restrict__ o)
{
    int row = blockIdx.x;
    int tid = threadIdx.x;
    const float4* xr = (const float4*)(x + (size_t)row * D_MODEL);
    float4 v = xr[tid];
    float s  = v.x + v.y + v.z + v.w;
    float ss = v.x*v.x + v.y*v.y + v.z*v.z + v.w*v.w;
    #pragma unroll
    for (int of = 16; of; of >>= 1) {
        s  += __shfl_xor_sync(0xffffffffu, s,  of);
        ss += __shfl_xor_sync(0xffffffffu, ss, of);
    }
    __shared__ float rs[8], rss[8];
    int w = tid >> 5;
    if ((tid & 31) == 0) { rs[w] = s; rss[w] = ss; }
    __syncthreads();
    float S0 = 0.f, SS0 = 0.f;
    #pragma unroll
    for (int i = 0; i < 8; i++) { S0 += rs[i]; SS0 += rss[i]; }
    float mean = S0 * (1.0f / D_MODEL);
    float var  = SS0 * (1.0f / D_MODEL) - mean * mean;
    float rstd = rsqrtf(var + 1e-5f);
    float4 gg = ((const float4*)gamma)[tid];
    float4 bb = ((const float4*)beta)[tid];
    float o0 = (v.x - mean) * rstd * gg.x + bb.x;
    float o1 = (v.y - mean) * rstd * gg.y + bb.y;
    float o2 = (v.z - mean) * rstd * gg.z + bb.z;
    float o3 = (v.w - mean) * rstd * gg.w + bb.w;
    size_t base = (size_t)row * D_MODEL + tid * 4;
    *(uint2*)&o[base] = make_uint2(pack_h(o0, o1), pack_h(o2, o3));
}

// ---------------- fused preprocessing ----------------
#define PREP_BLOCKS 13437

__device__ __forceinline__ void transpose_blk(
    const float* __restrict__ src, __half* __restrict__ dst,
    int K, int N, int nb, int kb, int tx, int ty, float (*tile)[33])
{
    int n0 = nb * 32, k0 = kb * 32;
    #pragma unroll
    for (int r = 0; r < 4; r++)
        tile[ty + 8 * r][tx] = src[(size_t)(k0 + ty + 8 * r) * N + n0 + tx];
    __syncthreads();
    #pragma unroll
    for (int r = 0; r < 4; r++) {
        float v = tile[tx][ty + 8 * r];
        size_t o = (size_t)(n0 + ty + 8 * r) * K + k0 + tx;
        dst[o] = __float2half_rn(v);
    }
}

__global__ __launch_bounds__(256) void prep_kernel(
    const float* __restrict__ wq, const float* __restrict__ wk,
    const float* __restrict__ wv, const float* __restrict__ wo,
    const float* __restrict__ w1, const float* __restrict__ w2,
    __half* __restrict__ w,
    const float* __restrict__ bq, const float* __restrict__ bk,
    const float* __restrict__ bv, float* __restrict__ bqkv,
    const int* __restrict__ mask, unsigned long long* __restrict__ mpk,
    const float* __restrict__ bt, float* __restrict__ bt2)
{
    __shared__ float tile[32][33];
    int bid = blockIdx.x;
    int tx = threadIdx.x, ty = threadIdx.y;
    int ft = ty * 32 + tx;

    if (bid < 4096) {
        int which = bid >> 10, r = bid & 1023;
        const float* src = which == 0 ? wq : which == 1 ? wk : which == 2 ? wv : wo;
        transpose_blk(src, w + (size_t)which * MEG, 1024, 1024, r & 31, r >> 5, tx, ty, tile);
    } else if (bid < 8192) {
        int r = bid - 4096;
        transpose_blk(w1, w + 4 * MEG, 1024, 4096, r & 127, r >> 7, tx, ty, tile);
    } else if (bid < 12288) {
        int r = bid - 8192;
        transpose_blk(w2, w + 8 * MEG, 4096, 1024, r & 31, r >> 5, tx, ty, tile);
    } else if (bid < 12300) {
        int i = (bid - 12288) * 256 + ft;
        if (i < QKV_N)
            bqkv[i] = i < 1024 ? bq[i] : (i < 2048 ? bk[i - 1024] : bv[i - 2048]);
    } else if (bid < 12812) {
        int idx = (bid - 12300) * 256 + ft;
        const int4* p = (const int4*)mask + (size_t)idx * 16;
        unsigned long long wv64 = 0;
        #pragma unroll
        for (int i = 0; i < 16; i++) {
            int4 v = p[i];
            wv64 |= (unsigned long long)(v.x != 0) << (i * 4 + 0);
            wv64 |= (unsigned long long)(v.y != 0) << (i * 4 + 1);
            wv64 |= (unsigned long long)(v.z != 0) << (i * 4 + 2);
            wv64 |= (unsigned long long)(v.w != 0) << (i * 4 + 3);
        }
        mpk[idx] = wv64;
    } else {
        int i = (bid - 12812) * 256 + ft;
        if (i < BT_ELEMS)
            bt2[i] = bt[i] * 1.4426950408889634f - 6.0f;
    }
}

// ---------------- fp16 GEMM (2-stage cp.async pipeline — proven config) ----------------
// EPI: 1 bias+GELU -> fp16, 2 bias+residual -> fp32, 5 bias -> fp16
__device__ __forceinline__ float gelu_exact(float x) {
    return 0.5f * x * (1.0f + erff(x * 0.70710678118654752f));
}

#define GM_A     0
#define GM_B     16384
#define GM_SSZ   32768
#define GM_SMEM  (2 * GM_SSZ)

template<int EPI>
__global__ __launch_bounds__(256) void gemm_mma(
    const __half* __restrict__ A, const __half* __restrict__ B,
    const float* __restrict__ bias, const float* __restrict__ res,
    float* __restrict__ C, __half* __restrict__ Ch, int M, int N, int K)
{
    extern __shared__ char smem[];
    uint32_t base = smem_u32(smem);
    int tid  = threadIdx.x;
    int lane = tid & 31;
    int wid  = tid >> 5;
    int warp_m = wid & 3;
    int warp_n = wid >> 2;
    int bm = blockIdx.y * 128, bn = blockIdx.x * 128;

    float acc[2][8][4];
    #pragma unroll
    for (int i = 0; i < 2; i++)
        #pragma unroll
        for (int j = 0; j < 8; j++)
            #pragma unroll
            for (int t = 0; t < 4; t++) acc[i][j][t] = 0.f;

    auto load_tile = [&](uint32_t sdst, const __half* g, int rowBase, int k0) {
        #pragma unroll
        for (int i = 0; i < 4; i++) {
            int f = i * 256 + tid;
            int row = f >> 3, c = f & 7;
            const __half* gp = g + (size_t)(rowBase + row) * K + k0 + c * 8;
            uint32_t off = row * 128 + c * 16;
            uint32_t sw = off ^ ((off >> 3) & 0x70);
            CP_ASYNC16(sdst + sw, gp);
        }
    };
    auto load_chunk = [&](int stage, int k0) {
        uint32_t sb = base + stage * GM_SSZ;
        load_tile(sb + GM_A, A, bm, k0);
        load_tile(sb + GM_B, B, bn, k0);
        CP_COMMIT();
    };

    int a_row = warp_m * 32 + (lane & 15);
    int a_kh  = lane >> 4;
    int b_row = warp_n * 64 + ((lane >> 4) & 1) * 8 + (lane & 7);
    int b_kh  = (lane >> 3) & 1;

    int nCh = K >> 6;
    load_chunk(0, 0);

    for (int it = 0; it < nCh; it++) {
        int buf = it & 1;
        if (it + 1 < nCh) { load_chunk(buf ^ 1, (it + 1) << 6); CP_WAIT(1); }
        else              { CP_WAIT(0); }
        __syncthreads();

        uint32_t sb = base + buf * GM_SSZ;
        #pragma unroll
        for (int ks = 0; ks < 4; ks++) {
            uint32_t ah[2][4];
            #pragma unroll
            for (int mf = 0; mf < 2; mf++) {
                int row = a_row + mf * 16;
                uint32_t col = (uint32_t)((ks * 2 + a_kh) ^ (row & 7)) * 16;
                uint32_t ad = sb + GM_A + row * 128 + col;
                LDSM_X4(ah[mf][0], ah[mf][1], ah[mf][2], ah[mf][3], ad);
            }
            #pragma unroll
            for (int nfp = 0; nfp < 4; nfp++) {
                int row = b_row + nfp * 16;
                uint32_t col = (uint32_t)((ks * 2 + b_kh) ^ (row & 7)) * 16;
                uint32_t bh[4];
                uint32_t bd = sb + GM_B + row * 128 + col;
                LDSM_X4(bh[0], bh[1], bh[2], bh[3], bd);
                #pragma unroll
                for (int mf = 0; mf < 2; mf++) {
                    #pragma unroll
                    for (int nn = 0; nn < 2; nn++)
                        mma16816(acc[mf][nfp * 2 + nn], ah[mf], &bh[nn * 2]);
                }
            }
        }
        __syncthreads();
    }

    int mrow0 = bm + warp_m * 32 + (lane >> 2);
    int ncol0 = bn + warp_n * 64 + (lane & 3) * 2;
    #pragma unroll
    for (int mf = 0; mf < 2; mf++) {
        #pragma unroll
        for (int nf = 0; nf < 8; nf++) {
            int n = ncol0 + nf * 8;
            float b0 = bias[n], b1 = bias[n + 1];
            #pragma unroll
            for (int half = 0; half < 2; half++) {
                int m = mrow0 + mf * 16 + half * 8;
                float v0 = acc[mf][nf][half * 2 + 0] + b0;
                float v1 = acc[mf][nf][half * 2 + 1] + b1;
                size_t o = (size_t)m * N + n;
                if (EPI == 1) {
                    v0 = gelu_exact(v0); v1 = gelu_exact(v1);
                    *(uint32_t*)&Ch[o] = pack_h(v0, v1);
                } else if (EPI == 2) {
                    float2 rv = *(const float2*)&res[o];
                    *(float2*)&C[o] = make_float2(v0 + rv.x, v1 + rv.y);
                } else {
                    *(uint32_t*)&Ch[o] = pack_h(v0, v1);
                }
            }
        }
    }
}

// ---------------- flash attention (fp16 mma, no-max softmax, half-tile scores) ----------------
// grid (S/64, H, B), block 128 (4 warps x m16), 4 CTAs/SM (proven sweet spot)
#define AT_Q     0
#define AT_ST    8192
#define AT_K     0
#define AT_V     8192
#define AT_BIAS  16384
#define AT_SSZ   16896
#define AT_SMEM  (AT_ST + 2 * AT_SSZ)

__global__ __launch_bounds__(128, 4) void attn_mma(
    const __half* __restrict__ qkv, const float* __restrict__ bt2,
    const unsigned long long* __restrict__ mpk, __half* __restrict__ Oh)
{
    extern __shared__ char smem[];
    uint32_t base = smem_u32(smem);

    int b  = blockIdx.z, h = blockIdx.y;
    int q0 = blockIdx.x * 64;
    int tid  = threadIdx.x;
    int lane = tid & 31;
    int wid  = tid >> 5;
    int headoff = h * HEAD_D;

    // ---- Q tile load (64 x 64) ----
    #pragma unroll
    for (int i = 0; i < 4; i++) {
        int f = i * 128 + tid;
        int row = f >> 3, c = f & 7;
        uint32_t sw = row * 128 + (uint32_t)((c ^ (row & 7)) * 16);
        const __half* gp = qkv + ((size_t)(b * S_LEN + q0 + row)) * QKV_N + headoff + c * 8;
        CP_ASYNC16(base + AT_Q + sw, gp);
    }
    CP_COMMIT();

    auto load_kv = [&](int s, int kt) {
        uint32_t sb = base + AT_ST + s * AT_SSZ;
        int kr = kt * 64;
        #pragma unroll
        for (int i = 0; i < 4; i++) {
            int f = i * 128 + tid;
            int row = f >> 3, c = f & 7;
            uint32_t sw = row * 128 + (uint32_t)((c ^ (row & 7)) * 16);
            size_t gb = ((size_t)(b * S_LEN + kr + row)) * QKV_N + c * 8;
            CP_ASYNC16(sb + AT_K + sw, qkv + gb + 1024 + headoff);
            CP_ASYNC16(sb + AT_V + sw, qkv + gb + 2048 + headoff);
        }
        int d = kr - q0 + tid - 63 + MAXM1;
        CP_ASYNC4(sb + AT_BIAS + tid * 4, bt2 + (size_t)d * NUM_H + h);
        CP_COMMIT();
    };

    load_kv(0, 0);
    CP_WAIT(0);
    __syncthreads();

    // ---- hoist Q fragments ----
    int a_row = wid * 16 + (lane & 15);
    int a_kh  = lane >> 4;
    uint32_t qh[4][4];
    #pragma unroll
    for (int ks = 0; ks < 4; ks++) {
        uint32_t col = (uint32_t)(((ks * 2 + a_kh) ^ (a_row & 7)) * 16);
        uint32_t ad = base + AT_Q + a_row * 128 + col;
        LDSM_X4(qh[ks][0], qh[ks][1], qh[ks][2], qh[ks][3], ad);
    }

    float ctx[8][4];
    #pragma unroll
    for (int i = 0; i < 8; i++)
        #pragma unroll
        for (int j = 0; j < 4; j++) ctx[i][j] = 0.f;
    float l0 = 0.f, l1 = 0.f;

    int r_loc0 = wid * 16 + (lane >> 2);
    int cbase  = (lane & 3) * 2;
    int b_row_base = ((lane >> 4) & 1) * 8 + (lane & 7);
    int b_kh = (lane >> 3) & 1;
    int v_i  = lane >> 3, v_j = lane & 7;
    const float csc = 0.125f * 1.4426950408889634f;   // score scale in log2 domain

    const unsigned long long* mp0 = mpk + ((size_t)(b * S_LEN) + q0 + r_loc0) * (S_LEN / 64);
    const unsigned long long* mp1 = mpk + ((size_t)(b * S_LEN) + q0 + r_loc0 + 8) * (S_LEN / 64);

    const int nKT = S_LEN / 64;
    unsigned long long mw0 = mp0[0], mw1 = mp1[0];

    for (int kt = 0; kt < nKT; kt++) {
        int s = kt & 1;
        if (kt + 1 < nKT) { load_kv(s ^ 1, kt + 1); CP_WAIT(1); }
        else              { CP_WAIT(0); }
        __syncthreads();
        uint32_t sb = base + AT_ST + s * AT_SSZ;
        const float* bs = (const float*)(smem + AT_ST + s * AT_SSZ + AT_BIAS);

        bool allm = ((mw0 & mw1) == ~0ull);
        unsigned long long cw0 = mw0, cw1 = mw1;
        if (kt + 1 < nKT) { mw0 = mp0[kt + 1]; mw1 = mp1[kt + 1]; }

        #pragma unroll
        for (int ph = 0; ph < 2; ph++) {
            float sacc[4][4];
            #pragma unroll
            for (int i = 0; i < 4; i++)
                #pragma unroll
                for (int j = 0; j < 4; j++) sacc[i][j] = 0.f;

            #pragma unroll
            for (int ks = 0; ks < 4; ks++) {
                #pragma unroll
                for (int g2 = 0; g2 < 2; g2++) {
                    int g = ph * 2 + g2;
                    int row = g * 16 + b_row_base;
                    uint32_t col = (uint32_t)(((ks * 2 + b_kh) ^ (row & 7)) * 16);
                    uint32_t bh[4];
                    uint32_t bd = sb + AT_K + row * 128 + col;
                    LDSM_X4(bh[0], bh[1], bh[2], bh[3], bd);
                    mma16816(sacc[2*g2],   qh[ks], &bh[0]);
                    mma16816(sacc[2*g2+1], qh[ks], &bh[2]);
                }
            }

            float rs0 = 0.f, rs1 = 0.f;
            #pragma unroll
            for (int fl = 0; fl < 4; fl++) {
                int c0 = (ph * 4 + fl) * 8 + cbase;
                int i0 = c0 - r_loc0 + 63;
                float p00 = ex2f(sacc[fl][0] * csc + bs[i0]);
                float p01 = ex2f(sacc[fl][1] * csc + bs[i0 + 1]);
                float p10 = ex2f(sacc[fl][2] * csc + bs[i0 - 8]);
                float p11 = ex2f(sacc[fl][3] * csc + bs[i0 - 7]);
                if (!allm) {
                    p00 = ((cw0 >> c0) & 1)       ? p00 : 0.f;
                    p01 = ((cw0 >> (c0 + 1)) & 1) ? p01 : 0.f;
                    p10 = ((cw1 >> c0) & 1)       ? p10 : 0.f;
                    p11 = ((cw1 >> (c0 + 1)) & 1) ? p11 : 0.f;
                }
                sacc[fl][0] = p00; sacc[fl][1] = p01; sacc[fl][2] = p10; sacc[fl][3] = p11;
                rs0 += p00 + p01; rs1 += p10 + p11;
            }
            l0 += rs0; l1 += rs1;

            #pragma unroll
            for (int ksl = 0; ksl < 2; ksl++) {
                int ks = ph * 2 + ksl;
                uint32_t pf[4];
                pf[0] = pack_h(sacc[2*ksl][0],   sacc[2*ksl][1]);
                pf[1] = pack_h(sacc[2*ksl][2],   sacc[2*ksl][3]);
                pf[2] = pack_h(sacc[2*ksl+1][0], sacc[2*ksl+1][1]);
                pf[3] = pack_h(sacc[2*ksl+1][2], sacc[2*ksl+1][3]);
                #pragma unroll
                for (int vg = 0; vg < 4; vg++) {
                    int row = ks * 16 + (v_i & 1) * 8 + v_j;
                    uint32_t chunk = (uint32_t)(vg * 2 + (v_i >> 1));
                    uint32_t vd = sb + AT_V + row * 128 + ((chunk ^ (row & 7)) * 16);
                    uint32_t vb[4];
                    LDSM_X4_T(vb[0], vb[1], vb[2], vb[3], vd);
                    mma16816(ctx[2*vg],   pf, &vb[0]);
                    mma16816(ctx[2*vg+1], pf, &vb[2]);
                }
            }
        }
        __syncthreads();
    }

    l0 += __shfl_xor_sync(0xffffffffu, l0, 1);
    l0 += __shfl_xor_sync(0xffffffffu, l0, 2);
    l1 += __shfl_xor_sync(0xffffffffu, l1, 1);
    l1 += __shfl_xor_sync(0xffffffffu, l1, 2);

    float inv0 = 1.0f / l0, inv1 = 1.0f / l1;
    size_t tok0 = (size_t)(b * S_LEN + q0 + r_loc0);
    #pragma unroll
    for (int nf = 0; nf < 8; nf++) {
        int col = headoff + nf * 8 + cbase;
        *(uint32_t*)&Oh[tok0 * D_MODEL + col]       = pack_h(ctx[nf][0] * inv0, ctx[nf][1] * inv0);
        *(uint32_t*)&Oh[(tok0 + 8) * D_MODEL + col] = pack_h(ctx[nf][2] * inv1, ctx[nf][3] * inv1);
    }
}

// ---------------- host orchestration ----------------
extern "C" void kernel_launch(void* const* d_in, const int* in_sizes, int n_in,
                              void* d_out, int out_size)
{
    const float* x    = (const float*)d_in[0];
    const int*   mask = (const int*)  d_in[1];
    const float* wq = (const float*)d_in[2];
    const float* bq = (const float*)d_in[3];
    const float* wk = (const float*)d_in[4];
    const float* bk = (const float*)d_in[5];
    const float* wv = (const float*)d_in[6];
    const float* bv = (const float*)d_in[7];
    const float* wo = (const float*)d_in[8];
    const float* bo = (const float*)d_in[9];
    const float* w1 = (const float*)d_in[10];
    const float* b1 = (const float*)d_in[11];
    const float* w2 = (const float*)d_in[12];
    const float* b2 = (const float*)d_in[13];
    const float* g1  = (const float*)d_in[14];
    const float* be1 = (const float*)d_in[15];
    const float* g2  = (const float*)d_in[16];
    const float* be2 = (const float*)d_in[17];
    const float* bt  = (const float*)d_in[18];

    float *x1, *bqkv, *bt2;
    __half *a, *qkv, *c, *hbuf, *w;
    unsigned long long* mpk;
    cudaGetSymbolAddress((void**)&x1,   g_x1);
    cudaGetSymbolAddress((void**)&bqkv, g_bqkv);
    cudaGetSymbolAddress((void**)&bt2,  g_bt2);
    cudaGetSymbolAddress((void**)&a,    g_a);
    cudaGetSymbolAddress((void**)&qkv,  g_qkv);
    cudaGetSymbolAddress((void**)&c,    g_c);
    cudaGetSymbolAddress((void**)&hbuf, g_h);
    cudaGetSymbolAddress((void**)&w,    g_w);
    cudaGetSymbolAddress((void**)&mpk,  g_mpk);

    float* out = (float*)d_out;

    cudaFuncSetAttribute(gemm_mma<1>, cudaFuncAttributeMaxDynamicSharedMemorySize, GM_SMEM);
    cudaFuncSetAttribute(gemm_mma<2>, cudaFuncAttributeMaxDynamicSharedMemorySize, GM_SMEM);
    cudaFuncSetAttribute(gemm_mma<5>, cudaFuncAttributeMaxDynamicSharedMemorySize, GM_SMEM);
    cudaFuncSetAttribute(attn_mma,    cudaFuncAttributeMaxDynamicSharedMemorySize, AT_SMEM);

    // 0. pre-norm 1 -> fp16 ; fused preprocessing (separate kernels — proven layout)
    ln_kernel<<<N_TOK, 256>>>(x, g1, be1, a);
    prep_kernel<<<PREP_BLOCKS, dim3(32, 8)>>>(wq, wk, wv, wo, w1, w2, w,
                                              bq, bk, bv, bqkv, mask, mpk, bt, bt2);

    // 1. fused QKV projection -> interleaved [tok, 3072]
    gemm_mma<5><<<dim3(QKV_N / 128, N_TOK / 128), 256, GM_SMEM>>>(
        a, w, bqkv, nullptr, nullptr, qkv, N_TOK, QKV_N, D_MODEL);

    // 2. attention (64-row q tiles, no-max softmax, 4 CTA/SM)
    attn_mma<<<dim3(S_LEN / 64, NUM_H, B_SZ), 128, AT_SMEM>>>(qkv, bt2, mpk, c);

    // 3. output projection + residual(x) -> x1 fp32
    dim3 gproj(D_MODEL / 128, N_TOK / 128);
    gemm_mma<2><<<gproj, 256, GM_SMEM>>>(c, w + 3 * MEG, bo, x, x1, nullptr, N_TOK, D_MODEL, D_MODEL);

    // 4. pre-norm 2 -> fp16
    ln_kernel<<<N_TOK, 256>>>(x1, g2, be2, a);

    // 5. FFN up + GELU -> fp16
    gemm_mma<1><<<dim3(FF_DIM / 128, N_TOK / 128), 256, GM_SMEM>>>(
        a, w + 4 * MEG, b1, nullptr, nullptr, hbuf, N_TOK, FF_DIM, D_MODEL);

    // 6. FFN down + residual(x1) -> out
    gemm_mma<2><<<gproj, 256, GM_SMEM>>>(hbuf, w + 8 * MEG, b2, x1, out, nullptr, N_TOK, D_MODEL, FF_DIM);

    (void)in_sizes; (void)n_in; (void)out_size;
}